// round 9
// baseline (speedup 1.0000x reference)
#include <cuda_runtime.h>
#include <cuda_fp16.h>

#define M_DIM 2048
#define N_DIM 8192
#define N_ITERS 1000
#define TAU 1e-4f
#define SIGMA 1e-4f
#define NBLK 148
#define NTHR 1024

#define PROWS 13            // panel rows resident in SMEM
#define RPAD 14             // rows processed per block (13 panel + 1 register)

// ---------------- device globals (allocation-free scratch) ----------------
__device__ float g_xbar[N_DIM];
__device__ float g_lam[M_DIM];
__device__ float g_part[2][NBLK * N_DIM];           // double-buffered partials
__device__ unsigned g_bar[NBLK * 32];               // full-barrier flags (1/line)
__device__ unsigned g_xf[NBLK * 32];                // xbar-ready flags (1/line)
__device__ __half2 g_Ah[(size_t)M_DIM * N_DIM / 2]; // fp16 A (32 MB)

// ---------------- smem layout (bytes) ----------------
#define OFF_PANEL 0                        // 13 rows x 8192 half = 212992
#define OFF_RED   (PROWS * N_DIM * 2)      // 16x64 fp32 = 4096
#define OFF_Y     (OFF_RED + 4096)         // 16 fp32
#define OFF_X     (OFF_Y + 64)             // 64 fp32
#define OFF_C     (OFF_X + 256)            // 64 fp32
#define OFF_B     (OFF_C + 256)            // 16 fp32
#define SMEM_BYTES (OFF_B + 64)
#define OFF_LAM   0                        // finale reuse of panel: 2048 fp32

// ---------------------------------------------------------------------------
__global__ void init_kernel() {
    int i = blockIdx.x * blockDim.x + threadIdx.x;
    if (i < N_DIM) g_xbar[i] = 0.f;
    if (i < NBLK * 32) { g_bar[i] = 0u; g_xf[i] = 0u; }
}

__global__ void __launch_bounds__(256) convert_kernel(const float* __restrict__ A) {
    size_t i = (size_t)blockIdx.x * 256 + threadIdx.x;   // over float4s
    const float4* A4 = reinterpret_cast<const float4*>(A);
    float4 v = A4[i];
    g_Ah[2 * i]     = __floats2half2_rn(v.x, v.y);
    g_Ah[2 * i + 1] = __floats2half2_rn(v.z, v.w);
}

// ---- release/acquire flag ops (GPU scope), DeepEP-style -------------------
__device__ __forceinline__ void st_rel(unsigned* p, unsigned v) {
    asm volatile("st.release.gpu.global.u32 [%0], %1;" :: "l"(p), "r"(v) : "memory");
}
__device__ __forceinline__ unsigned ld_acq(unsigned* p) {
    unsigned v;
    asm volatile("ld.acquire.gpu.global.u32 %0, [%1];" : "=r"(v) : "l"(p) : "memory");
    return v;
}

// convert 8 fp16 (uint4) -> 8 fp32
__device__ __forceinline__ void cvt8(uint4 a, float* f) {
    float2 t;
    t = __half22float2(*reinterpret_cast<__half2*>(&a.x)); f[0] = t.x; f[1] = t.y;
    t = __half22float2(*reinterpret_cast<__half2*>(&a.y)); f[2] = t.x; f[3] = t.y;
    t = __half22float2(*reinterpret_cast<__half2*>(&a.z)); f[4] = t.x; f[5] = t.y;
    t = __half22float2(*reinterpret_cast<__half2*>(&a.w)); f[6] = t.x; f[7] = t.y;
}

__device__ __forceinline__ unsigned long long pack2(float lo, float hi) {
    unsigned long long r;
    asm("mov.b64 %0, {%1, %2};" : "=l"(r) : "f"(lo), "f"(hi));
    return r;
}
__device__ __forceinline__ void unpack2(unsigned long long v, float& lo, float& hi) {
    asm("mov.b64 {%0, %1}, %2;" : "=f"(lo), "=f"(hi) : "l"(v));
}
__device__ __forceinline__ void ffma2(unsigned long long& acc,
                                      unsigned long long a, unsigned long long b) {
    asm("fma.rn.f32x2 %0, %1, %2, %0;" : "+l"(acc) : "l"(a), "l"(b));
}

// ---------------------------------------------------------------------------
__global__ void __launch_bounds__(NTHR, 1)
pdhg_kernel(const float* __restrict__ A, const float* __restrict__ b,
            const float* __restrict__ c, float* __restrict__ out) {
    extern __shared__ char sm[];
    const int tid  = threadIdx.x;
    const int warp = tid >> 5;
    const int lane = tid & 31;
    const int blk  = blockIdx.x;

    // balanced ownership
    const int r0 = (blk * M_DIM) / NBLK;
    const int nr = ((blk + 1) * M_DIM) / NBLK - r0;   // 13 or 14
    const int c0 = (blk * N_DIM) / NBLK;
    const int nc = ((blk + 1) * N_DIM) / NBLK - c0;   // 55 or 56

    // owners of this thread's xbar columns (8t .. 8t+7)
    const int o1 = (148 * (8 * tid) + 147) >> 13;
    const int o2 = (148 * (8 * tid + 7) + 147) >> 13;

    float* s_red = (float*)(sm + OFF_RED);
    float* y_sm  = (float*)(sm + OFF_Y);
    float* x_sm  = (float*)(sm + OFF_X);
    float* c_sm  = (float*)(sm + OFF_C);
    float* b_sm  = (float*)(sm + OFF_B);
    const uint4* GA4 = reinterpret_cast<const uint4*>(g_Ah);
    const uint4* P4  = (const uint4*)(sm + OFF_PANEL);

    // ---- prologue: 13 panel rows -> SMEM; 14th row -> registers forever ----
    {
        uint4* W4 = (uint4*)(sm + OFF_PANEL);
        #pragma unroll
        for (int r = 0; r < PROWS; r++)
            W4[r * 1024 + tid] = GA4[((size_t)(r0 + r)) * 1024 + tid];
        if (tid < 16) y_sm[tid] = 0.f;
        if (tid < nr) b_sm[tid] = b[r0 + tid];
        if (tid < nc) { x_sm[tid] = 0.f; c_sm[tid] = c[c0 + tid]; }
    }
    const uint4 a_stream = GA4[((size_t)(r0 + PROWS)) * 1024 + tid];
    __syncthreads();

    for (int it = 0; it < N_ITERS; it++) {
        // ---- wait for this thread's xbar segment owners (fine-grained) ----
        if (it > 0) {
            while (ld_acq(&g_xf[o1 * 32]) < (unsigned)it) { }
            if (o2 != o1)
                while (ld_acq(&g_xf[o2 * 32]) < (unsigned)it) { }
        }

        // ================= Phase Y: y = min(0, y + s*(A@xbar) - s*b) =======
        float v[16];
        {
            const float4* gx4 = (const float4*)g_xbar;
            float4 xa = __ldcg(gx4 + 2 * tid);
            float4 xb = __ldcg(gx4 + 2 * tid + 1);
            unsigned long long xv2[8];
            xv2[0] = pack2(xa.x, xa.x); xv2[1] = pack2(xa.y, xa.y);
            xv2[2] = pack2(xa.z, xa.z); xv2[3] = pack2(xa.w, xa.w);
            xv2[4] = pack2(xb.x, xb.x); xv2[5] = pack2(xb.y, xb.y);
            xv2[6] = pack2(xb.z, xb.z); xv2[7] = pack2(xb.w, xb.w);

            unsigned long long acc2[7];
            #pragma unroll
            for (int p = 0; p < 7; p++) {
                uint4 ua = P4[(2 * p) * 1024 + tid];
                uint4 ub = (2 * p + 1 < PROWS) ? P4[(2 * p + 1) * 1024 + tid]
                                               : a_stream;
                float fa[8], fb[8];
                cvt8(ua, fa); cvt8(ub, fb);
                unsigned long long acc = 0ull;
                #pragma unroll
                for (int k = 0; k < 8; k++)
                    ffma2(acc, pack2(fa[k], fb[k]), xv2[k]);
                acc2[p] = acc;
            }
            #pragma unroll
            for (int p = 0; p < 7; p++) unpack2(acc2[p], v[2 * p], v[2 * p + 1]);
            v[14] = 0.f; v[15] = 0.f;
        }
        // butterfly multi-row warp reduction: 16 rows -> per-warp partials
        {
            #pragma unroll
            for (int k = 0; k < 8; k++) {
                float s = (lane & 16) ? v[k] : v[k + 8];
                float r = __shfl_xor_sync(0xffffffffu, s, 16);
                v[k] = ((lane & 16) ? v[k + 8] : v[k]) + r;
            }
            #pragma unroll
            for (int k = 0; k < 4; k++) {
                float s = (lane & 8) ? v[k] : v[k + 4];
                float r = __shfl_xor_sync(0xffffffffu, s, 8);
                v[k] = ((lane & 8) ? v[k + 4] : v[k]) + r;
            }
            #pragma unroll
            for (int k = 0; k < 2; k++) {
                float s = (lane & 4) ? v[k] : v[k + 2];
                float r = __shfl_xor_sync(0xffffffffu, s, 4);
                v[k] = ((lane & 4) ? v[k + 2] : v[k]) + r;
            }
            {
                float s = (lane & 2) ? v[0] : v[1];
                float r = __shfl_xor_sync(0xffffffffu, s, 2);
                v[0] = ((lane & 2) ? v[1] : v[0]) + r;
            }
            v[0] += __shfl_xor_sync(0xffffffffu, v[0], 1);
            int row = (((lane >> 4) & 1) << 3) | (((lane >> 3) & 1) << 2) |
                      (((lane >> 2) & 1) << 1) | ((lane >> 1) & 1);
            if ((lane & 1) == 0) s_red[row * 32 + warp] = v[0];
        }
        __syncthreads();
        if (warp < 16) {
            float t = s_red[warp * 32 + lane];
            #pragma unroll
            for (int o = 16; o > 0; o >>= 1)
                t += __shfl_down_sync(0xffffffffu, t, o);
            if (lane == 0 && warp < nr)
                y_sm[warp] = fminf(0.f, y_sm[warp] + SIGMA * t - SIGMA * b_sm[warp]);
        }
        __syncthreads();

        // ============ Phase X partials: part[j] = sum_i A[i][j]*y[i] =======
        {
            unsigned long long xacc[4] = {0ull, 0ull, 0ull, 0ull};
            #pragma unroll
            for (int i = 0; i < RPAD; i++) {
                float yv = y_sm[i];
                unsigned long long yv2 = pack2(yv, yv);
                uint4 a = (i < PROWS) ? P4[i * 1024 + tid] : a_stream;
                float f[8];
                cvt8(a, f);
                ffma2(xacc[0], pack2(f[0], f[1]), yv2);
                ffma2(xacc[1], pack2(f[2], f[3]), yv2);
                ffma2(xacc[2], pack2(f[4], f[5]), yv2);
                ffma2(xacc[3], pack2(f[6], f[7]), yv2);
            }
            float o0, o1f, o2f, o3, o4, o5, o6, o7;
            unpack2(xacc[0], o0, o1f); unpack2(xacc[1], o2f, o3);
            unpack2(xacc[2], o4, o5);  unpack2(xacc[3], o6, o7);
            float4* O4 = (float4*)(g_part[it & 1] + (size_t)blk * N_DIM + tid * 8);
            __stcg(O4,     make_float4(o0, o1f, o2f, o3));
            __stcg(O4 + 1, make_float4(o4, o5, o6, o7));
        }

        // ---- full barrier #1: all partials of this iter visible ----
        __syncthreads();
        if (tid == 0) st_rel(&g_bar[blk * 32], (unsigned)(it + 1));
        if (tid < NBLK) {
            while (ld_acq(&g_bar[tid * 32]) < (unsigned)(it + 1)) { }
        }
        __syncthreads();

        // ===== Reduce 148 partials for this block's nc columns =============
        {
            const float* buf = g_part[it & 1];
            int g  = tid >> 6;
            int jc = tid & 63;
            if (jc < nc) {
                float r = 0.f;
                for (int p = g; p < NBLK; p += 16)
                    r += __ldcg(buf + (size_t)p * N_DIM + c0 + jc);
                s_red[g * 64 + jc] = r;
            }
            __syncthreads();
            if (tid < nc) {
                float dot = 0.f;
                #pragma unroll
                for (int gg = 0; gg < 16; gg++) dot += s_red[gg * 64 + tid];
                float xo = x_sm[tid];
                float xn = fmaxf(0.f, xo - TAU * dot - TAU * c_sm[tid]);
                x_sm[tid] = xn;
                __stcg(&g_xbar[c0 + tid], 2.f * xn - xo);
            }
        }
        __syncthreads();
        if (tid == 0) st_rel(&g_xf[blk * 32], (unsigned)(it + 1));
    }

    // ---- Finalize: out = [x, lam, nu] ----
    if (tid < nc) out[c0 + tid] = x_sm[tid];
    if (tid < nr) {
        float l = fmaxf(0.f, -y_sm[tid]);
        __stcg(&g_lam[r0 + tid], l);
        out[N_DIM + r0 + tid] = l;
    }
    __syncthreads();
    if (tid == 0) st_rel(&g_bar[blk * 32], (unsigned)(N_ITERS + 1));
    if (tid < NBLK) {
        while (ld_acq(&g_bar[tid * 32]) < (unsigned)(N_ITERS + 1)) { }
    }
    __syncthreads();

    // nu = relu(c - A^T @ lam), against ORIGINAL fp32 A (one pass, accuracy)
    {
        float* s_lam = (float*)(sm + OFF_LAM);
        #pragma unroll
        for (int t = 0; t < 2; t++) {
            int i = t * NTHR + tid;
            if (i < M_DIM) s_lam[i] = __ldcg(&g_lam[i]);
        }
        __syncthreads();

        int g  = tid >> 6;
        int jc = tid & 63;
        if (jc < nc) {
            float acc = 0.f;
            for (int i = g; i < M_DIM; i += 16)
                acc += A[(size_t)i * N_DIM + c0 + jc] * s_lam[i];
            s_red[g * 64 + jc] = acc;
        }
        __syncthreads();
        if (tid < nc) {
            float dot = 0.f;
            #pragma unroll
            for (int gg = 0; gg < 16; gg++) dot += s_red[gg * 64 + tid];
            out[N_DIM + M_DIM + c0 + tid] = fmaxf(0.f, c_sm[tid] - dot);
        }
    }
}

// ---------------------------------------------------------------------------
// kernel_launch: 3 graph nodes. Inputs (metadata order):
//   d_in[0] = c (8192), d_in[1] = A (2048*8192), d_in[2] = b (2048)
// Output: 18432 floats = concat(x[8192], lam[2048], nu[8192])
// ---------------------------------------------------------------------------
extern "C" void kernel_launch(void* const* d_in, const int* in_sizes, int n_in,
                              void* d_out, int out_size) {
    const float* c = (const float*)d_in[0];
    const float* A = (const float*)d_in[1];
    const float* b = (const float*)d_in[2];
    float* out = (float*)d_out;

    cudaFuncSetAttribute(pdhg_kernel,
                         cudaFuncAttributeMaxDynamicSharedMemorySize, SMEM_BYTES);

    init_kernel<<<32, 256>>>();
    convert_kernel<<<(M_DIM * N_DIM / 4) / 256, 256>>>(A);
    pdhg_kernel<<<NBLK, NTHR, SMEM_BYTES>>>(A, b, c, out);
}

// round 10
// speedup vs baseline: 1.0135x; 1.0135x over previous
#include <cuda_runtime.h>
#include <cuda_fp16.h>

#define M_DIM 2048
#define N_DIM 8192
#define N_ITERS 1000
#define TAU 1e-4f
#define SIGMA 1e-4f
#define NBLK 148
#define NTHR 1024

#define R32 6               // fp32 rows in SMEM (exact, from original A)
#define R16 2               // fp16 rows in SMEM
#define RSM (R32 + R16)     // 8 rows in SMEM
#define RPAD 14             // rows processed per block (6..13 streamed/padded)

// ---------------- device globals (allocation-free scratch) ----------------
__device__ float g_xbar[N_DIM];
__device__ float g_lam[M_DIM];
__device__ float g_part[NBLK * N_DIM];              // fp32 partials
__device__ volatile unsigned g_flags[NBLK * 32];    // 1 flag / 128B line
__device__ __half2 g_Ah[(size_t)M_DIM * N_DIM / 2]; // fp16 A (32 MB)

// ---------------- smem layout (bytes) ----------------
#define OFF_P32   0                        // 6 rows x 8192 fp32 = 196608
#define OFF_P16   196608                   // 2 rows x 8192 fp16 = 32768
#define OFF_RED   229376                   // 2048 B scratch (16x32 / 8x64 fp32)
#define OFF_Y     231424                   // 16 fp32
#define OFF_X     231488                   // 64 fp32
#define OFF_C     231744                   // 64 fp32
#define OFF_B     232000                   // 16 fp32
#define SMEM_BYTES 232064                  // <= 232448 (227 KB cap)
#define OFF_LAM   0                        // finale reuse: 2048 fp32

// ---------------------------------------------------------------------------
__global__ void init_kernel() {
    int i = blockIdx.x * blockDim.x + threadIdx.x;
    if (i < N_DIM) g_xbar[i] = 0.f;
    if (i < NBLK * 32) g_flags[i] = 0u;
}

__global__ void __launch_bounds__(256) convert_kernel(const float* __restrict__ A) {
    size_t i = (size_t)blockIdx.x * 256 + threadIdx.x;   // over float4s
    const float4* A4 = reinterpret_cast<const float4*>(A);
    float4 v = A4[i];
    g_Ah[2 * i]     = __floats2half2_rn(v.x, v.y);
    g_Ah[2 * i + 1] = __floats2half2_rn(v.z, v.w);
}

// ---------------------------------------------------------------------------
// R8 barrier (proven): release fence + flag store; 148 pollers on volatile
// loads; acquire fence (L1D invalidate) before reading cross-block data.
// ---------------------------------------------------------------------------
__device__ __forceinline__ void grid_barrier(unsigned target) {
    __syncthreads();
    if (threadIdx.x == 0) {
        __threadfence();
        g_flags[blockIdx.x * 32] = target;
    }
    if (threadIdx.x < NBLK) {
        while (g_flags[threadIdx.x * 32] < target) { }
    }
    __syncthreads();
    if (threadIdx.x == 0) __threadfence();
    __syncthreads();
}

// convert 8 fp16 (uint4) -> 8 fp32
__device__ __forceinline__ void cvt8(uint4 a, float* f) {
    float2 t;
    t = __half22float2(*reinterpret_cast<__half2*>(&a.x)); f[0] = t.x; f[1] = t.y;
    t = __half22float2(*reinterpret_cast<__half2*>(&a.y)); f[2] = t.x; f[3] = t.y;
    t = __half22float2(*reinterpret_cast<__half2*>(&a.z)); f[4] = t.x; f[5] = t.y;
    t = __half22float2(*reinterpret_cast<__half2*>(&a.w)); f[6] = t.x; f[7] = t.y;
}

__device__ __forceinline__ float dotf8(const float* f, float4 xa, float4 xb) {
    return f[0] * xa.x + f[1] * xa.y + f[2] * xa.z + f[3] * xa.w +
           f[4] * xb.x + f[5] * xb.y + f[6] * xb.z + f[7] * xb.w;
}

// ---------------------------------------------------------------------------
__global__ void __launch_bounds__(NTHR, 1)
pdhg_kernel(const float* __restrict__ A, const float* __restrict__ b,
            const float* __restrict__ c, float* __restrict__ out) {
    extern __shared__ char sm[];
    const int tid  = threadIdx.x;
    const int warp = tid >> 5;
    const int lane = tid & 31;
    const int blk  = blockIdx.x;

    const int r0 = (blk * M_DIM) / NBLK;
    const int nr = ((blk + 1) * M_DIM) / NBLK - r0;   // 13 or 14
    const int c0 = (blk * N_DIM) / NBLK;
    const int nc = ((blk + 1) * N_DIM) / NBLK - c0;   // 55 or 56

    float* s_red = (float*)(sm + OFF_RED);
    float* y_sm  = (float*)(sm + OFF_Y);
    float* x_sm  = (float*)(sm + OFF_X);
    float* c_sm  = (float*)(sm + OFF_C);
    float* b_sm  = (float*)(sm + OFF_B);
    const uint4* GA4 = reinterpret_cast<const uint4*>(g_Ah);

    // ---- prologue ----
    {
        // 6 fp32 rows straight from original A (exact)
        float4* W = (float4*)(sm + OFF_P32);
        const float4* A4 = (const float4*)A;
        #pragma unroll
        for (int r = 0; r < R32; r++) {
            W[r * 2048 + tid]        = A4[((size_t)(r0 + r)) * 2048 + tid];
            W[r * 2048 + 1024 + tid] = A4[((size_t)(r0 + r)) * 2048 + 1024 + tid];
        }
        // 2 fp16 rows
        uint4* H = (uint4*)(sm + OFF_P16);
        #pragma unroll
        for (int r = 0; r < R16; r++)
            H[r * 1024 + tid] = GA4[((size_t)(r0 + R32 + r)) * 1024 + tid];
        if (tid < 16) y_sm[tid] = 0.f;
        if (tid < nr) b_sm[tid] = b[r0 + tid];
        if (tid < nc) { x_sm[tid] = 0.f; c_sm[tid] = c[c0 + tid]; }
    }
    __syncthreads();

    unsigned epoch = 0;

    for (int it = 0; it < N_ITERS; it++) {
        // ================= Phase Y: y = min(0, y + s*(A@xbar) - s*b) =======
        float v[16];
        {
            const float4* gx4 = (const float4*)g_xbar;
            float4 xa = gx4[2 * tid];
            float4 xb = gx4[2 * tid + 1];

            // fp32 SMEM rows 0..5 (no conversion)
            #pragma unroll
            for (int i = 0; i < R32; i++) {
                const float4* R = (const float4*)(sm + OFF_P32 + i * 32768) + 2 * tid;
                float4 a0 = R[0], a1 = R[1];
                v[i] = a0.x * xa.x + a0.y * xa.y + a0.z * xa.z + a0.w * xa.w +
                       a1.x * xb.x + a1.y * xb.y + a1.z * xb.z + a1.w * xb.w;
            }
            // fp16 SMEM rows 6..7
            #pragma unroll
            for (int i = 0; i < R16; i++) {
                uint4 a = *((const uint4*)(sm + OFF_P16 + i * 16384) + tid);
                float f[8]; cvt8(a, f);
                v[R32 + i] = dotf8(f, xa, xb);
            }
            // streamed fp16 rows 8..13, batched 3+3 for MLP
            {
                uint4 s0 = GA4[((size_t)(r0 +  8)) * 1024 + tid];
                uint4 s1 = GA4[((size_t)(r0 +  9)) * 1024 + tid];
                uint4 s2 = GA4[((size_t)(r0 + 10)) * 1024 + tid];
                float f[8];
                cvt8(s0, f); v[8]  = dotf8(f, xa, xb);
                cvt8(s1, f); v[9]  = dotf8(f, xa, xb);
                cvt8(s2, f); v[10] = dotf8(f, xa, xb);
                uint4 s3 = GA4[((size_t)(r0 + 11)) * 1024 + tid];
                uint4 s4 = GA4[((size_t)(r0 + 12)) * 1024 + tid];
                uint4 s5 = GA4[((size_t)(r0 + 13)) * 1024 + tid];
                cvt8(s3, f); v[11] = dotf8(f, xa, xb);
                cvt8(s4, f); v[12] = dotf8(f, xa, xb);
                cvt8(s5, f); v[13] = dotf8(f, xa, xb);
            }
            v[14] = 0.f; v[15] = 0.f;
        }
        // butterfly multi-row warp reduction (R8-proven)
        {
            #pragma unroll
            for (int k = 0; k < 8; k++) {
                float s = (lane & 16) ? v[k] : v[k + 8];
                float r = __shfl_xor_sync(0xffffffffu, s, 16);
                v[k] = ((lane & 16) ? v[k + 8] : v[k]) + r;
            }
            #pragma unroll
            for (int k = 0; k < 4; k++) {
                float s = (lane & 8) ? v[k] : v[k + 4];
                float r = __shfl_xor_sync(0xffffffffu, s, 8);
                v[k] = ((lane & 8) ? v[k + 4] : v[k]) + r;
            }
            #pragma unroll
            for (int k = 0; k < 2; k++) {
                float s = (lane & 4) ? v[k] : v[k + 2];
                float r = __shfl_xor_sync(0xffffffffu, s, 4);
                v[k] = ((lane & 4) ? v[k + 2] : v[k]) + r;
            }
            {
                float s = (lane & 2) ? v[0] : v[1];
                float r = __shfl_xor_sync(0xffffffffu, s, 2);
                v[0] = ((lane & 2) ? v[1] : v[0]) + r;
            }
            v[0] += __shfl_xor_sync(0xffffffffu, v[0], 1);
            int row = (((lane >> 4) & 1) << 3) | (((lane >> 3) & 1) << 2) |
                      (((lane >> 2) & 1) << 1) | ((lane >> 1) & 1);
            if ((lane & 1) == 0) s_red[row * 32 + warp] = v[0];
        }
        __syncthreads();
        if (warp < 16) {
            float t = s_red[warp * 32 + lane];
            #pragma unroll
            for (int o = 16; o > 0; o >>= 1)
                t += __shfl_down_sync(0xffffffffu, t, o);
            if (lane == 0 && warp < nr)
                y_sm[warp] = fminf(0.f, y_sm[warp] + SIGMA * t - SIGMA * b_sm[warp]);
        }
        __syncthreads();

        // ============ Phase X partials: part[j] = sum_i A[i][j]*y[i] =======
        {
            float o0 = 0.f, o1 = 0.f, o2 = 0.f, o3 = 0.f;
            float o4 = 0.f, o5 = 0.f, o6 = 0.f, o7 = 0.f;
            // fp32 SMEM rows
            #pragma unroll
            for (int i = 0; i < R32; i++) {
                float yv = y_sm[i];
                const float4* R = (const float4*)(sm + OFF_P32 + i * 32768) + 2 * tid;
                float4 a0 = R[0], a1 = R[1];
                o0 += a0.x * yv; o1 += a0.y * yv; o2 += a0.z * yv; o3 += a0.w * yv;
                o4 += a1.x * yv; o5 += a1.y * yv; o6 += a1.z * yv; o7 += a1.w * yv;
            }
            // fp16 SMEM rows
            #pragma unroll
            for (int i = 0; i < R16; i++) {
                float yv = y_sm[R32 + i];
                uint4 a = *((const uint4*)(sm + OFF_P16 + i * 16384) + tid);
                float f[8]; cvt8(a, f);
                o0 += f[0] * yv; o1 += f[1] * yv; o2 += f[2] * yv; o3 += f[3] * yv;
                o4 += f[4] * yv; o5 += f[5] * yv; o6 += f[6] * yv; o7 += f[7] * yv;
            }
            // streamed rows 8..13 (y_sm[13] == 0 for padded blocks)
            #pragma unroll
            for (int s = 0; s < 6; s++) {
                float yv = y_sm[8 + s];
                uint4 a = GA4[((size_t)(r0 + 8 + s)) * 1024 + tid];
                float f[8]; cvt8(a, f);
                o0 += f[0] * yv; o1 += f[1] * yv; o2 += f[2] * yv; o3 += f[3] * yv;
                o4 += f[4] * yv; o5 += f[5] * yv; o6 += f[6] * yv; o7 += f[7] * yv;
            }
            float4* O4 = (float4*)(g_part + (size_t)blk * N_DIM + tid * 8);
            O4[0] = make_float4(o0, o1, o2, o3);
            O4[1] = make_float4(o4, o5, o6, o7);
        }
        grid_barrier(++epoch);

        // ===== Reduce 148 partials for this block's nc columns (8 groups) ==
        {
            int g  = tid >> 6;        // 0..15, use 0..7
            int jc = tid & 63;
            if (g < 8 && jc < nc) {
                float r = 0.f;
                #pragma unroll 4
                for (int p = g; p < NBLK; p += 8)
                    r += g_part[(size_t)p * N_DIM + c0 + jc];
                s_red[g * 64 + jc] = r;
            }
            __syncthreads();
            if (tid < nc) {
                float dot = 0.f;
                #pragma unroll
                for (int gg = 0; gg < 8; gg++) dot += s_red[gg * 64 + tid];
                float xo = x_sm[tid];
                float xn = fmaxf(0.f, xo - TAU * dot - TAU * c_sm[tid]);
                x_sm[tid] = xn;
                g_xbar[c0 + tid] = 2.f * xn - xo;
            }
        }
        grid_barrier(++epoch);
    }

    // ---- Finalize: out = [x, lam, nu] ----
    if (tid < nc) out[c0 + tid] = x_sm[tid];
    if (tid < nr) {
        float l = fmaxf(0.f, -y_sm[tid]);
        g_lam[r0 + tid] = l;
        out[N_DIM + r0 + tid] = l;
    }
    grid_barrier(++epoch);

    // nu = relu(c - A^T @ lam), against ORIGINAL fp32 A
    {
        float* s_lam = (float*)(sm + OFF_LAM);
        #pragma unroll
        for (int t = 0; t < 2; t++) {
            int i = t * NTHR + tid;
            if (i < M_DIM) s_lam[i] = g_lam[i];
        }
        __syncthreads();

        int g  = tid >> 6;        // 0..15, use 0..7
        int jc = tid & 63;
        if (g < 8 && jc < nc) {
            float acc = 0.f;
            for (int i = g; i < M_DIM; i += 8)
                acc += A[(size_t)i * N_DIM + c0 + jc] * s_lam[i];
            s_red[g * 64 + jc] = acc;
        }
        __syncthreads();
        if (tid < nc) {
            float dot = 0.f;
            #pragma unroll
            for (int gg = 0; gg < 8; gg++) dot += s_red[gg * 64 + tid];
            out[N_DIM + M_DIM + c0 + tid] = fmaxf(0.f, c_sm[tid] - dot);
        }
    }
}

// ---------------------------------------------------------------------------
// kernel_launch: 3 graph nodes. Inputs (metadata order):
//   d_in[0] = c (8192), d_in[1] = A (2048*8192), d_in[2] = b (2048)
// Output: 18432 floats = concat(x[8192], lam[2048], nu[8192])
// ---------------------------------------------------------------------------
extern "C" void kernel_launch(void* const* d_in, const int* in_sizes, int n_in,
                              void* d_out, int out_size) {
    const float* c = (const float*)d_in[0];
    const float* A = (const float*)d_in[1];
    const float* b = (const float*)d_in[2];
    float* out = (float*)d_out;

    cudaFuncSetAttribute(pdhg_kernel,
                         cudaFuncAttributeMaxDynamicSharedMemorySize, SMEM_BYTES);

    init_kernel<<<32, 256>>>();
    convert_kernel<<<(M_DIM * N_DIM / 4) / 256, 256>>>(A);
    pdhg_kernel<<<NBLK, NTHR, SMEM_BYTES>>>(A, b, c, out);
}

// round 11
// speedup vs baseline: 1.1306x; 1.1156x over previous
#include <cuda_runtime.h>
#include <cuda_fp16.h>

#define M_DIM 2048
#define N_DIM 8192
#define N_ITERS 1000
#define TAU 1e-4f
#define SIGMA 1e-4f
#define NBLK 148
#define NTHR 1024

#define PROWS 13            // panel rows resident in SMEM
#define SCALE112 5.192296858534828e+33f   // 2^112

// ---------------- device globals (allocation-free scratch) ----------------
__device__ float g_xbar[N_DIM];
__device__ float g_lam[M_DIM];
__device__ float g_part[NBLK * N_DIM];              // fp32 partials
__device__ volatile unsigned g_flags[NBLK * 32];    // 1 flag / 128B line
__device__ __half2 g_Ah[(size_t)M_DIM * N_DIM / 2]; // fp16 A (32 MB)

// ---------------- smem layout (bytes) ----------------
#define OFF_PANEL 0                        // 13 rows x 8192 half = 212992
#define OFF_RED   (PROWS * N_DIM * 2)      // 16x64 fp32 = 4096
#define OFF_Y     (OFF_RED + 4096)         // 16 fp32
#define OFF_X     (OFF_Y + 64)             // 64 fp32
#define OFF_C     (OFF_X + 256)            // 64 fp32
#define OFF_B     (OFF_C + 256)            // 16 fp32
#define SMEM_BYTES (OFF_B + 64)
#define OFF_LAM   0                        // finale reuse of panel: 2048 fp32

// ---------------------------------------------------------------------------
__global__ void init_kernel() {
    int i = blockIdx.x * blockDim.x + threadIdx.x;
    if (i < N_DIM) g_xbar[i] = 0.f;
    if (i < NBLK * 32) g_flags[i] = 0u;
}

__global__ void __launch_bounds__(256) convert_kernel(const float* __restrict__ A) {
    size_t i = (size_t)blockIdx.x * 256 + threadIdx.x;   // over float4s
    const float4* A4 = reinterpret_cast<const float4*>(A);
    float4 v = A4[i];
    g_Ah[2 * i]     = __floats2half2_rn(v.x, v.y);
    g_Ah[2 * i + 1] = __floats2half2_rn(v.z, v.w);
}

// ---------------------------------------------------------------------------
// R8 barrier (best known): release fence + flag store; 148 pollers on
// volatile loads; acquire fence (L1D invalidate) before cross-block reads.
// ---------------------------------------------------------------------------
__device__ __forceinline__ void grid_barrier(unsigned target) {
    __syncthreads();
    if (threadIdx.x == 0) {
        __threadfence();
        g_flags[blockIdx.x * 32] = target;
    }
    if (threadIdx.x < NBLK) {
        while (g_flags[threadIdx.x * 32] < target) { }
    }
    __syncthreads();
    if (threadIdx.x == 0) __threadfence();
    __syncthreads();
}

// ---------------------------------------------------------------------------
// Conversion-free fp16 expansion: h (normal) -> f32 bits of value*2^-112.
//   f0 = ((r<<13)&0x0FFFE000) | ((r<<16)&0x80000000)      (low half)
//   f1 = ((r>>3) &0x0FFFE000) | ( r     &0x80000000)      (high half)
// Exact for normal fp16; fp16 subnormals (|A|<6.1e-5) flush ~0 (negligible).
// 3 SHF + 2 LOP3 per half2, all full-rate ALU — no F2F.
// ---------------------------------------------------------------------------
__device__ __forceinline__ void expand2(unsigned r, float& f0, float& f1) {
    unsigned u0 = ((r << 13) & 0x0FFFE000u) | ((r << 16) & 0x80000000u);
    unsigned u1 = ((r >> 3)  & 0x0FFFE000u) | (r & 0x80000000u);
    f0 = __uint_as_float(u0);
    f1 = __uint_as_float(u1);
}
__device__ __forceinline__ void expand8(uint4 a, float* f) {
    expand2(a.x, f[0], f[1]);
    expand2(a.y, f[2], f[3]);
    expand2(a.z, f[4], f[5]);
    expand2(a.w, f[6], f[7]);
}

// ---------------------------------------------------------------------------
__global__ void __launch_bounds__(NTHR, 1)
pdhg_kernel(const float* __restrict__ A, const float* __restrict__ b,
            const float* __restrict__ c, float* __restrict__ out) {
    extern __shared__ char sm[];
    const int tid  = threadIdx.x;
    const int warp = tid >> 5;
    const int lane = tid & 31;
    const int blk  = blockIdx.x;

    const int r0 = (blk * M_DIM) / NBLK;
    const int nr = ((blk + 1) * M_DIM) / NBLK - r0;   // 13 or 14
    const int c0 = (blk * N_DIM) / NBLK;
    const int nc = ((blk + 1) * N_DIM) / NBLK - c0;   // 55 or 56

    float* s_red = (float*)(sm + OFF_RED);
    float* y_sm  = (float*)(sm + OFF_Y);
    float* x_sm  = (float*)(sm + OFF_X);
    float* c_sm  = (float*)(sm + OFF_C);
    float* b_sm  = (float*)(sm + OFF_B);
    const uint4* GA4 = reinterpret_cast<const uint4*>(g_Ah);
    const uint4* P4  = (const uint4*)(sm + OFF_PANEL);

    // ---- prologue: 13 panel rows -> SMEM; 14th row -> registers forever ----
    {
        uint4* W4 = (uint4*)(sm + OFF_PANEL);
        #pragma unroll
        for (int r = 0; r < PROWS; r++)
            W4[r * 1024 + tid] = GA4[((size_t)(r0 + r)) * 1024 + tid];
        if (tid < 16) y_sm[tid] = 0.f;
        if (tid < nr) b_sm[tid] = b[r0 + tid];
        if (tid < nc) { x_sm[tid] = 0.f; c_sm[tid] = c[c0 + tid]; }
    }
    const uint4 a_stream = GA4[((size_t)(r0 + PROWS)) * 1024 + tid];  // row 13
    __syncthreads();

    unsigned epoch = 0;

    for (int it = 0; it < N_ITERS; it++) {
        // ================= Phase Y: y = min(0, y + s*(A@xbar) - s*b) =======
        float v[16];
        {
            const float4* gx4 = (const float4*)g_xbar;
            float4 xa = gx4[2 * tid];
            float4 xb = gx4[2 * tid + 1];
            float xs[8];
            xs[0] = xa.x * SCALE112; xs[1] = xa.y * SCALE112;
            xs[2] = xa.z * SCALE112; xs[3] = xa.w * SCALE112;
            xs[4] = xb.x * SCALE112; xs[5] = xb.y * SCALE112;
            xs[6] = xb.z * SCALE112; xs[7] = xb.w * SCALE112;

            #pragma unroll
            for (int p = 0; p < 7; p++) {
                uint4 ua = P4[(2 * p) * 1024 + tid];
                uint4 ub = (2 * p + 1 < PROWS) ? P4[(2 * p + 1) * 1024 + tid]
                                               : a_stream;
                float fa[8], fb[8];
                expand8(ua, fa); expand8(ub, fb);
                float s0 = 0.f, s1 = 0.f;
                #pragma unroll
                for (int k = 0; k < 8; k++) {
                    s0 += fa[k] * xs[k];
                    s1 += fb[k] * xs[k];
                }
                v[2 * p]     = s0;
                v[2 * p + 1] = s1;
            }
            v[14] = 0.f; v[15] = 0.f;
        }
        // butterfly multi-row warp reduction (R8-proven)
        {
            #pragma unroll
            for (int k = 0; k < 8; k++) {
                float s = (lane & 16) ? v[k] : v[k + 8];
                float r = __shfl_xor_sync(0xffffffffu, s, 16);
                v[k] = ((lane & 16) ? v[k + 8] : v[k]) + r;
            }
            #pragma unroll
            for (int k = 0; k < 4; k++) {
                float s = (lane & 8) ? v[k] : v[k + 4];
                float r = __shfl_xor_sync(0xffffffffu, s, 8);
                v[k] = ((lane & 8) ? v[k + 4] : v[k]) + r;
            }
            #pragma unroll
            for (int k = 0; k < 2; k++) {
                float s = (lane & 4) ? v[k] : v[k + 2];
                float r = __shfl_xor_sync(0xffffffffu, s, 4);
                v[k] = ((lane & 4) ? v[k + 2] : v[k]) + r;
            }
            {
                float s = (lane & 2) ? v[0] : v[1];
                float r = __shfl_xor_sync(0xffffffffu, s, 2);
                v[0] = ((lane & 2) ? v[1] : v[0]) + r;
            }
            v[0] += __shfl_xor_sync(0xffffffffu, v[0], 1);
            int row = (((lane >> 4) & 1) << 3) | (((lane >> 3) & 1) << 2) |
                      (((lane >> 2) & 1) << 1) | ((lane >> 1) & 1);
            if ((lane & 1) == 0) s_red[row * 32 + warp] = v[0];
        }
        __syncthreads();
        if (warp < 16) {
            float t = s_red[warp * 32 + lane];
            #pragma unroll
            for (int o = 16; o > 0; o >>= 1)
                t += __shfl_down_sync(0xffffffffu, t, o);
            if (lane == 0 && warp < nr)
                y_sm[warp] = fminf(0.f, y_sm[warp] + SIGMA * t - SIGMA * b_sm[warp]);
        }
        __syncthreads();

        // ============ Phase X partials: part[j] = sum_i A[i][j]*y[i] =======
        {
            float o0 = 0.f, o1 = 0.f, o2 = 0.f, o3 = 0.f;
            float o4 = 0.f, o5 = 0.f, o6 = 0.f, o7 = 0.f;
            #pragma unroll
            for (int i = 0; i < 14; i++) {
                float ys = y_sm[i] * SCALE112;         // 0 for padded row
                uint4 a = (i < PROWS) ? P4[i * 1024 + tid] : a_stream;
                float f[8];
                expand8(a, f);
                o0 += f[0] * ys; o1 += f[1] * ys; o2 += f[2] * ys; o3 += f[3] * ys;
                o4 += f[4] * ys; o5 += f[5] * ys; o6 += f[6] * ys; o7 += f[7] * ys;
            }
            float4* O4 = (float4*)(g_part + (size_t)blk * N_DIM + tid * 8);
            O4[0] = make_float4(o0, o1, o2, o3);
            O4[1] = make_float4(o4, o5, o6, o7);
        }
        grid_barrier(++epoch);

        // ===== Reduce 148 partials for this block's nc columns =============
        {
            int g  = tid >> 6;
            int jc = tid & 63;
            if (jc < nc) {
                float r = 0.f;
                #pragma unroll
                for (int k = 0; k < 10; k++) {         // 148/16 -> 9 or 10
                    int p = g + k * 16;
                    if (p < NBLK)
                        r += g_part[(size_t)p * N_DIM + c0 + jc];
                }
                s_red[g * 64 + jc] = r;
            }
            __syncthreads();
            if (tid < nc) {
                float dot = 0.f;
                #pragma unroll
                for (int gg = 0; gg < 16; gg++) dot += s_red[gg * 64 + tid];
                float xo = x_sm[tid];
                float xn = fmaxf(0.f, xo - TAU * dot - TAU * c_sm[tid]);
                x_sm[tid] = xn;
                g_xbar[c0 + tid] = 2.f * xn - xo;
            }
        }
        grid_barrier(++epoch);
    }

    // ---- Finalize: out = [x, lam, nu] ----
    if (tid < nc) out[c0 + tid] = x_sm[tid];
    if (tid < nr) {
        float l = fmaxf(0.f, -y_sm[tid]);
        g_lam[r0 + tid] = l;
        out[N_DIM + r0 + tid] = l;
    }
    grid_barrier(++epoch);

    // nu = relu(c - A^T @ lam), against ORIGINAL fp32 A (one pass, accuracy)
    {
        float* s_lam = (float*)(sm + OFF_LAM);
        #pragma unroll
        for (int t = 0; t < 2; t++) {
            int i = t * NTHR + tid;
            if (i < M_DIM) s_lam[i] = g_lam[i];
        }
        __syncthreads();

        int g  = tid >> 6;
        int jc = tid & 63;
        if (jc < nc) {
            float acc = 0.f;
            for (int i = g; i < M_DIM; i += 16)
                acc += A[(size_t)i * N_DIM + c0 + jc] * s_lam[i];
            s_red[g * 64 + jc] = acc;
        }
        __syncthreads();
        if (tid < nc) {
            float dot = 0.f;
            #pragma unroll
            for (int gg = 0; gg < 16; gg++) dot += s_red[gg * 64 + tid];
            out[N_DIM + M_DIM + c0 + tid] = fmaxf(0.f, c_sm[tid] - dot);
        }
    }
}

// ---------------------------------------------------------------------------
// kernel_launch: 3 graph nodes. Inputs (metadata order):
//   d_in[0] = c (8192), d_in[1] = A (2048*8192), d_in[2] = b (2048)
// Output: 18432 floats = concat(x[8192], lam[2048], nu[8192])
// ---------------------------------------------------------------------------
extern "C" void kernel_launch(void* const* d_in, const int* in_sizes, int n_in,
                              void* d_out, int out_size) {
    const float* c = (const float*)d_in[0];
    const float* A = (const float*)d_in[1];
    const float* b = (const float*)d_in[2];
    float* out = (float*)d_out;

    cudaFuncSetAttribute(pdhg_kernel,
                         cudaFuncAttributeMaxDynamicSharedMemorySize, SMEM_BYTES);

    init_kernel<<<32, 256>>>();
    convert_kernel<<<(M_DIM * N_DIM / 4) / 256, 256>>>(A);
    pdhg_kernel<<<NBLK, NTHR, SMEM_BYTES>>>(A, b, c, out);
}

// round 12
// speedup vs baseline: 1.2404x; 1.0971x over previous
#include <cuda_runtime.h>
#include <cuda_fp16.h>

#define M_DIM 2048
#define N_DIM 8192
#define N_ITERS 1000
#define TAU 1e-4f
#define SIGMA 1e-4f
#define NBLK 148
#define NTHR 1024

#define PROWS 13            // panel rows resident in SMEM (+1 register row)

// ---------------- device globals (allocation-free scratch) ----------------
__device__ float g_xbar[N_DIM];
__device__ float g_lam[M_DIM];
__device__ float g_part[NBLK * N_DIM];              // fp32 partials
__device__ volatile unsigned g_flags[NBLK * 32];    // 1 flag / 128B line

// ---------------- smem layout (bytes) ----------------
#define OFF_PANEL 0                        // 13 rows x 8192 half = 212992
#define OFF_RED   (PROWS * N_DIM * 2)      // 16x64 fp32 = 4096
#define OFF_Y     (OFF_RED + 4096)         // 16 fp32
#define OFF_X     (OFF_Y + 64)             // 64 fp32
#define OFF_C     (OFF_X + 256)            // 64 fp32
#define OFF_B     (OFF_C + 256)            // 16 fp32
#define SMEM_BYTES (OFF_B + 64)
#define OFF_LAM   0                        // finale reuse of panel: 2048 fp32

// ---------------------------------------------------------------------------
// Graph node 1: zero xbar + barrier flags (MUST precede pdhg each replay so
// monotonic-epoch flags never carry stale values across replays)
// ---------------------------------------------------------------------------
__global__ void init_kernel() {
    int i = blockIdx.x * blockDim.x + threadIdx.x;
    if (i < N_DIM) g_xbar[i] = 0.f;
    if (i < NBLK * 32) g_flags[i] = 0u;
}

// ---------------------------------------------------------------------------
// R8 barrier (best known): release fence + flag store; 148 pollers on
// volatile loads; acquire fence (L1D invalidate) before cross-block reads.
// ---------------------------------------------------------------------------
__device__ __forceinline__ void grid_barrier(unsigned target) {
    __syncthreads();
    if (threadIdx.x == 0) {
        __threadfence();
        g_flags[blockIdx.x * 32] = target;
    }
    if (threadIdx.x < NBLK) {
        while (g_flags[threadIdx.x * 32] < target) { }
    }
    __syncthreads();
    if (threadIdx.x == 0) __threadfence();
    __syncthreads();
}

// convert 8 fp16 (uint4) -> 8 fp32
__device__ __forceinline__ void cvt8(uint4 a, float* f) {
    float2 t;
    t = __half22float2(*reinterpret_cast<__half2*>(&a.x)); f[0] = t.x; f[1] = t.y;
    t = __half22float2(*reinterpret_cast<__half2*>(&a.y)); f[2] = t.x; f[3] = t.y;
    t = __half22float2(*reinterpret_cast<__half2*>(&a.z)); f[4] = t.x; f[5] = t.y;
    t = __half22float2(*reinterpret_cast<__half2*>(&a.w)); f[6] = t.x; f[7] = t.y;
}

// pack 8 fp32 -> uint4 of fp16 (same rounding as prior convert_kernel)
__device__ __forceinline__ uint4 pack8(float4 v0, float4 v1) {
    uint4 h;
    *reinterpret_cast<__half2*>(&h.x) = __floats2half2_rn(v0.x, v0.y);
    *reinterpret_cast<__half2*>(&h.y) = __floats2half2_rn(v0.z, v0.w);
    *reinterpret_cast<__half2*>(&h.z) = __floats2half2_rn(v1.x, v1.y);
    *reinterpret_cast<__half2*>(&h.w) = __floats2half2_rn(v1.z, v1.w);
    return h;
}

// ---------------------------------------------------------------------------
__global__ void __launch_bounds__(NTHR, 1)
pdhg_kernel(const float* __restrict__ A, const float* __restrict__ b,
            const float* __restrict__ c, float* __restrict__ out) {
    extern __shared__ char sm[];
    const int tid  = threadIdx.x;
    const int warp = tid >> 5;
    const int lane = tid & 31;
    const int blk  = blockIdx.x;

    const int r0 = (blk * M_DIM) / NBLK;
    const int nr = ((blk + 1) * M_DIM) / NBLK - r0;   // 13 or 14
    const int c0 = (blk * N_DIM) / NBLK;
    const int nc = ((blk + 1) * N_DIM) / NBLK - c0;   // 55 or 56

    float* s_red = (float*)(sm + OFF_RED);
    float* y_sm  = (float*)(sm + OFF_Y);
    float* x_sm  = (float*)(sm + OFF_X);
    float* c_sm  = (float*)(sm + OFF_C);
    float* b_sm  = (float*)(sm + OFF_B);
    const uint4* P4 = (const uint4*)(sm + OFF_PANEL);

    // ---- prologue: convert this block's 13 fp32 rows -> fp16 SMEM panel;
    //      14th row -> fp16 registers forever. (g_Ah eliminated)
    {
        const float4* A4 = (const float4*)A;
        uint4* W4 = (uint4*)(sm + OFF_PANEL);
        for (int r = 0; r < PROWS; r++) {
            float4 v0 = A4[((size_t)(r0 + r)) * 2048 + 2 * tid];
            float4 v1 = A4[((size_t)(r0 + r)) * 2048 + 2 * tid + 1];
            W4[r * 1024 + tid] = pack8(v0, v1);
        }
        if (tid < 16) y_sm[tid] = 0.f;
        if (tid < nr) b_sm[tid] = b[r0 + tid];
        if (tid < nc) { x_sm[tid] = 0.f; c_sm[tid] = c[c0 + tid]; }
    }
    uint4 a_stream;
    {
        const float4* A4 = (const float4*)A;
        float4 v0 = A4[((size_t)(r0 + PROWS)) * 2048 + 2 * tid];
        float4 v1 = A4[((size_t)(r0 + PROWS)) * 2048 + 2 * tid + 1];
        a_stream = pack8(v0, v1);
    }
    __syncthreads();

    unsigned epoch = 0;

    for (int it = 0; it < N_ITERS; it++) {
        // ================= Phase Y: y = min(0, y + s*(A@xbar) - s*b) =======
        float v[16];
        {
            const float4* gx4 = (const float4*)g_xbar;
            float4 xa = gx4[2 * tid];
            float4 xb = gx4[2 * tid + 1];

            // one row at a time: single f[8] buffer, ~50 live regs (no spill)
            #pragma unroll
            for (int i = 0; i < 14; i++) {
                uint4 a = (i < PROWS) ? P4[i * 1024 + tid] : a_stream;
                float f[8];
                cvt8(a, f);
                v[i] = f[0] * xa.x + f[1] * xa.y + f[2] * xa.z + f[3] * xa.w +
                       f[4] * xb.x + f[5] * xb.y + f[6] * xb.z + f[7] * xb.w;
            }
            v[14] = 0.f; v[15] = 0.f;
        }
        // butterfly multi-row warp reduction (R8-proven)
        {
            #pragma unroll
            for (int k = 0; k < 8; k++) {
                float s = (lane & 16) ? v[k] : v[k + 8];
                float r = __shfl_xor_sync(0xffffffffu, s, 16);
                v[k] = ((lane & 16) ? v[k + 8] : v[k]) + r;
            }
            #pragma unroll
            for (int k = 0; k < 4; k++) {
                float s = (lane & 8) ? v[k] : v[k + 4];
                float r = __shfl_xor_sync(0xffffffffu, s, 8);
                v[k] = ((lane & 8) ? v[k + 4] : v[k]) + r;
            }
            #pragma unroll
            for (int k = 0; k < 2; k++) {
                float s = (lane & 4) ? v[k] : v[k + 2];
                float r = __shfl_xor_sync(0xffffffffu, s, 4);
                v[k] = ((lane & 4) ? v[k + 2] : v[k]) + r;
            }
            {
                float s = (lane & 2) ? v[0] : v[1];
                float r = __shfl_xor_sync(0xffffffffu, s, 2);
                v[0] = ((lane & 2) ? v[1] : v[0]) + r;
            }
            v[0] += __shfl_xor_sync(0xffffffffu, v[0], 1);
            int row = (((lane >> 4) & 1) << 3) | (((lane >> 3) & 1) << 2) |
                      (((lane >> 2) & 1) << 1) | ((lane >> 1) & 1);
            if ((lane & 1) == 0) s_red[row * 32 + warp] = v[0];
        }
        __syncthreads();
        if (warp < 16) {
            float t = s_red[warp * 32 + lane];
            #pragma unroll
            for (int o = 16; o > 0; o >>= 1)
                t += __shfl_down_sync(0xffffffffu, t, o);
            if (lane == 0 && warp < nr)
                y_sm[warp] = fminf(0.f, y_sm[warp] + SIGMA * t - SIGMA * b_sm[warp]);
        }
        __syncthreads();

        // ============ Phase X partials: part[j] = sum_i A[i][j]*y[i] =======
        {
            float o0 = 0.f, o1 = 0.f, o2 = 0.f, o3 = 0.f;
            float o4 = 0.f, o5 = 0.f, o6 = 0.f, o7 = 0.f;
            #pragma unroll
            for (int i = 0; i < 14; i++) {
                float yv = y_sm[i];                    // 0 for padded row
                uint4 a = (i < PROWS) ? P4[i * 1024 + tid] : a_stream;
                float f[8];
                cvt8(a, f);
                o0 += f[0] * yv; o1 += f[1] * yv; o2 += f[2] * yv; o3 += f[3] * yv;
                o4 += f[4] * yv; o5 += f[5] * yv; o6 += f[6] * yv; o7 += f[7] * yv;
            }
            float4* O4 = (float4*)(g_part + (size_t)blk * N_DIM + tid * 8);
            O4[0] = make_float4(o0, o1, o2, o3);
            O4[1] = make_float4(o4, o5, o6, o7);
        }
        grid_barrier(++epoch);

        // ===== Reduce 148 partials for this block's nc columns =============
        {
            int g  = tid >> 6;
            int jc = tid & 63;
            if (jc < nc) {
                float r = 0.f;
                #pragma unroll
                for (int k = 0; k < 10; k++) {         // 148/16 -> 9 or 10
                    int p = g + k * 16;
                    if (p < NBLK)
                        r += g_part[(size_t)p * N_DIM + c0 + jc];
                }
                s_red[g * 64 + jc] = r;
            }
            __syncthreads();
            if (tid < nc) {
                float dot = 0.f;
                #pragma unroll
                for (int gg = 0; gg < 16; gg++) dot += s_red[gg * 64 + tid];
                float xo = x_sm[tid];
                float xn = fmaxf(0.f, xo - TAU * dot - TAU * c_sm[tid]);
                x_sm[tid] = xn;
                g_xbar[c0 + tid] = 2.f * xn - xo;
            }
        }
        grid_barrier(++epoch);
    }

    // ---- Finalize: out = [x, lam, nu] ----
    if (tid < nc) out[c0 + tid] = x_sm[tid];
    if (tid < nr) {
        float l = fmaxf(0.f, -y_sm[tid]);
        g_lam[r0 + tid] = l;
        out[N_DIM + r0 + tid] = l;
    }
    grid_barrier(++epoch);

    // nu = relu(c - A^T @ lam), against ORIGINAL fp32 A (one pass, accuracy)
    {
        float* s_lam = (float*)(sm + OFF_LAM);
        #pragma unroll
        for (int t = 0; t < 2; t++) {
            int i = t * NTHR + tid;
            if (i < M_DIM) s_lam[i] = g_lam[i];
        }
        __syncthreads();

        int g  = tid >> 6;
        int jc = tid & 63;
        if (jc < nc) {
            float acc = 0.f;
            for (int i = g; i < M_DIM; i += 16)
                acc += A[(size_t)i * N_DIM + c0 + jc] * s_lam[i];
            s_red[g * 64 + jc] = acc;
        }
        __syncthreads();
        if (tid < nc) {
            float dot = 0.f;
            #pragma unroll
            for (int gg = 0; gg < 16; gg++) dot += s_red[gg * 64 + tid];
            out[N_DIM + M_DIM + c0 + tid] = fmaxf(0.f, c_sm[tid] - dot);
        }
    }
}

// ---------------------------------------------------------------------------
// kernel_launch: 2 graph nodes (init, pdhg). Inputs (metadata order):
//   d_in[0] = c (8192), d_in[1] = A (2048*8192), d_in[2] = b (2048)
// Output: 18432 floats = concat(x[8192], lam[2048], nu[8192])
// ---------------------------------------------------------------------------
extern "C" void kernel_launch(void* const* d_in, const int* in_sizes, int n_in,
                              void* d_out, int out_size) {
    const float* c = (const float*)d_in[0];
    const float* A = (const float*)d_in[1];
    const float* b = (const float*)d_in[2];
    float* out = (float*)d_out;

    cudaFuncSetAttribute(pdhg_kernel,
                         cudaFuncAttributeMaxDynamicSharedMemorySize, SMEM_BYTES);

    init_kernel<<<32, 256>>>();
    pdhg_kernel<<<NBLK, NTHR, SMEM_BYTES>>>(A, b, c, out);
}

// round 13
// speedup vs baseline: 1.2745x; 1.0275x over previous
#include <cuda_runtime.h>
#include <cuda_fp16.h>

#define M_DIM 2048
#define N_DIM 8192
#define N_ITERS 1000
#define TAU 1e-4f
#define SIGMA 1e-4f
#define NBLK 148
#define NTHR 1024

#define PROWS 13            // panel rows resident in SMEM (+1 register row)

// ---------------- device globals (allocation-free scratch) ----------------
__device__ float g_xbar[N_DIM];
__device__ float g_lam[M_DIM];
__device__ float g_part[NBLK * N_DIM];    // fp32 partials (L2-only traffic)
__device__ unsigned g_flags[NBLK * 32];   // 1 flag / 128B line

// ---------------- smem layout (bytes) ----------------
#define OFF_PANEL 0                        // 13 rows x 8192 half = 212992
#define OFF_RED   (PROWS * N_DIM * 2)      // 16x64 fp32 = 4096
#define OFF_Y     (OFF_RED + 4096)         // 16 fp32
#define OFF_X     (OFF_Y + 64)             // 64 fp32
#define OFF_C     (OFF_X + 256)            // 64 fp32
#define OFF_B     (OFF_C + 256)            // 16 fp32
#define SMEM_BYTES (OFF_B + 64)
#define OFF_LAM   0                        // finale reuse of panel: 2048 fp32

// ---------------------------------------------------------------------------
__global__ void init_kernel() {
    int i = blockIdx.x * blockDim.x + threadIdx.x;
    if (i < N_DIM) g_xbar[i] = 0.f;
    if (i < NBLK * 32) g_flags[i] = 0u;
}

// ---- GPU-scope sync primitives (no SYS-scope, no CCTL.IVALL) --------------
__device__ __forceinline__ unsigned ld_relaxed(const unsigned* p) {
    unsigned v;
    asm volatile("ld.relaxed.gpu.global.u32 %0, [%1];" : "=r"(v) : "l"(p) : "memory");
    return v;
}
__device__ __forceinline__ void st_release(unsigned* p, unsigned v) {
    asm volatile("st.release.gpu.global.u32 [%0], %1;" :: "l"(p), "r"(v) : "memory");
}
__device__ __forceinline__ void fence_acq() {
    asm volatile("fence.acq_rel.gpu;" ::: "memory");
}

// ---------------------------------------------------------------------------
// Lightweight grid barrier:
//   bar.sync (CTA-scope release of all threads' prior stores to thread 0)
//   -> st.release.gpu flag (orders the block's __stcg writes)
//   -> 148 pollers with ld.relaxed.gpu (GPU scope, cheap)
//   -> fence.acq_rel.gpu on exit, bar.sync propagates to whole block.
// Cross-block DATA uses __ldcg/__stcg (L2-coherent): no L1 staleness, so no
// membar.gl / CCTL.IVALL anywhere in the loop.
// ---------------------------------------------------------------------------
__device__ __forceinline__ void grid_barrier(unsigned target) {
    __syncthreads();
    if (threadIdx.x == 0)
        st_release(&g_flags[blockIdx.x * 32], target);
    if (threadIdx.x < NBLK) {
        while (ld_relaxed(&g_flags[threadIdx.x * 32]) < target) { }
        fence_acq();
    }
    __syncthreads();
}

// convert 8 fp16 (uint4) -> 8 fp32
__device__ __forceinline__ void cvt8(uint4 a, float* f) {
    float2 t;
    t = __half22float2(*reinterpret_cast<__half2*>(&a.x)); f[0] = t.x; f[1] = t.y;
    t = __half22float2(*reinterpret_cast<__half2*>(&a.y)); f[2] = t.x; f[3] = t.y;
    t = __half22float2(*reinterpret_cast<__half2*>(&a.z)); f[4] = t.x; f[5] = t.y;
    t = __half22float2(*reinterpret_cast<__half2*>(&a.w)); f[6] = t.x; f[7] = t.y;
}

// pack 8 fp32 -> uint4 of fp16
__device__ __forceinline__ uint4 pack8(float4 v0, float4 v1) {
    uint4 h;
    *reinterpret_cast<__half2*>(&h.x) = __floats2half2_rn(v0.x, v0.y);
    *reinterpret_cast<__half2*>(&h.y) = __floats2half2_rn(v0.z, v0.w);
    *reinterpret_cast<__half2*>(&h.z) = __floats2half2_rn(v1.x, v1.y);
    *reinterpret_cast<__half2*>(&h.w) = __floats2half2_rn(v1.z, v1.w);
    return h;
}

// ---------------------------------------------------------------------------
__global__ void __launch_bounds__(NTHR, 1)
pdhg_kernel(const float* __restrict__ A, const float* __restrict__ b,
            const float* __restrict__ c, float* __restrict__ out) {
    extern __shared__ char sm[];
    const int tid  = threadIdx.x;
    const int warp = tid >> 5;
    const int lane = tid & 31;
    const int blk  = blockIdx.x;

    const int r0 = (blk * M_DIM) / NBLK;
    const int nr = ((blk + 1) * M_DIM) / NBLK - r0;   // 13 or 14
    const int c0 = (blk * N_DIM) / NBLK;
    const int nc = ((blk + 1) * N_DIM) / NBLK - c0;   // 55 or 56

    float* s_red = (float*)(sm + OFF_RED);
    float* y_sm  = (float*)(sm + OFF_Y);
    float* x_sm  = (float*)(sm + OFF_X);
    float* c_sm  = (float*)(sm + OFF_C);
    float* b_sm  = (float*)(sm + OFF_B);
    const uint4* P4 = (const uint4*)(sm + OFF_PANEL);

    // ---- prologue: convert this block's 13 fp32 rows -> fp16 SMEM panel;
    //      14th row -> fp16 registers forever.
    {
        const float4* A4 = (const float4*)A;
        uint4* W4 = (uint4*)(sm + OFF_PANEL);
        for (int r = 0; r < PROWS; r++) {
            float4 v0 = A4[((size_t)(r0 + r)) * 2048 + 2 * tid];
            float4 v1 = A4[((size_t)(r0 + r)) * 2048 + 2 * tid + 1];
            W4[r * 1024 + tid] = pack8(v0, v1);
        }
        if (tid < 16) y_sm[tid] = 0.f;
        if (tid < nr) b_sm[tid] = b[r0 + tid];
        if (tid < nc) { x_sm[tid] = 0.f; c_sm[tid] = c[c0 + tid]; }
    }
    uint4 a_stream;
    {
        const float4* A4 = (const float4*)A;
        float4 v0 = A4[((size_t)(r0 + PROWS)) * 2048 + 2 * tid];
        float4 v1 = A4[((size_t)(r0 + PROWS)) * 2048 + 2 * tid + 1];
        a_stream = pack8(v0, v1);
    }
    __syncthreads();

    unsigned epoch = 0;

    for (int it = 0; it < N_ITERS; it++) {
        // ================= Phase Y: y = min(0, y + s*(A@xbar) - s*b) =======
        float v[16];
        {
            const float4* gx4 = (const float4*)g_xbar;
            float4 xa = __ldcg(gx4 + 2 * tid);        // L2-coherent read
            float4 xb = __ldcg(gx4 + 2 * tid + 1);

            #pragma unroll
            for (int i = 0; i < 14; i++) {
                uint4 a = (i < PROWS) ? P4[i * 1024 + tid] : a_stream;
                float f[8];
                cvt8(a, f);
                v[i] = f[0] * xa.x + f[1] * xa.y + f[2] * xa.z + f[3] * xa.w +
                       f[4] * xb.x + f[5] * xb.y + f[6] * xb.z + f[7] * xb.w;
            }
            v[14] = 0.f; v[15] = 0.f;
        }
        // butterfly multi-row warp reduction (R8-proven)
        {
            #pragma unroll
            for (int k = 0; k < 8; k++) {
                float s = (lane & 16) ? v[k] : v[k + 8];
                float r = __shfl_xor_sync(0xffffffffu, s, 16);
                v[k] = ((lane & 16) ? v[k + 8] : v[k]) + r;
            }
            #pragma unroll
            for (int k = 0; k < 4; k++) {
                float s = (lane & 8) ? v[k] : v[k + 4];
                float r = __shfl_xor_sync(0xffffffffu, s, 8);
                v[k] = ((lane & 8) ? v[k + 4] : v[k]) + r;
            }
            #pragma unroll
            for (int k = 0; k < 2; k++) {
                float s = (lane & 4) ? v[k] : v[k + 2];
                float r = __shfl_xor_sync(0xffffffffu, s, 4);
                v[k] = ((lane & 4) ? v[k + 2] : v[k]) + r;
            }
            {
                float s = (lane & 2) ? v[0] : v[1];
                float r = __shfl_xor_sync(0xffffffffu, s, 2);
                v[0] = ((lane & 2) ? v[1] : v[0]) + r;
            }
            v[0] += __shfl_xor_sync(0xffffffffu, v[0], 1);
            int row = (((lane >> 4) & 1) << 3) | (((lane >> 3) & 1) << 2) |
                      (((lane >> 2) & 1) << 1) | ((lane >> 1) & 1);
            if ((lane & 1) == 0) s_red[row * 32 + warp] = v[0];
        }
        __syncthreads();
        if (warp < 16) {
            float t = s_red[warp * 32 + lane];
            #pragma unroll
            for (int o = 16; o > 0; o >>= 1)
                t += __shfl_down_sync(0xffffffffu, t, o);
            if (lane == 0 && warp < nr)
                y_sm[warp] = fminf(0.f, y_sm[warp] + SIGMA * t - SIGMA * b_sm[warp]);
        }
        __syncthreads();

        // ============ Phase X partials: part[j] = sum_i A[i][j]*y[i] =======
        {
            float o0 = 0.f, o1 = 0.f, o2 = 0.f, o3 = 0.f;
            float o4 = 0.f, o5 = 0.f, o6 = 0.f, o7 = 0.f;
            #pragma unroll
            for (int i = 0; i < 14; i++) {
                float yv = y_sm[i];                    // 0 for padded row
                uint4 a = (i < PROWS) ? P4[i * 1024 + tid] : a_stream;
                float f[8];
                cvt8(a, f);
                o0 += f[0] * yv; o1 += f[1] * yv; o2 += f[2] * yv; o3 += f[3] * yv;
                o4 += f[4] * yv; o5 += f[5] * yv; o6 += f[6] * yv; o7 += f[7] * yv;
            }
            float4* O4 = (float4*)(g_part + (size_t)blk * N_DIM + tid * 8);
            __stcg(O4,     make_float4(o0, o1, o2, o3));   // L2-only store
            __stcg(O4 + 1, make_float4(o4, o5, o6, o7));
        }
        grid_barrier(++epoch);

        // ===== Reduce 148 partials for this block's nc columns =============
        {
            int g  = tid >> 6;
            int jc = tid & 63;
            if (jc < nc) {
                float r = 0.f;
                #pragma unroll
                for (int k = 0; k < 10; k++) {         // 148/16 -> 9 or 10
                    int p = g + k * 16;
                    if (p < NBLK)
                        r += __ldcg(g_part + (size_t)p * N_DIM + c0 + jc);
                }
                s_red[g * 64 + jc] = r;
            }
            __syncthreads();
            if (tid < nc) {
                float dot = 0.f;
                #pragma unroll
                for (int gg = 0; gg < 16; gg++) dot += s_red[gg * 64 + tid];
                float xo = x_sm[tid];
                float xn = fmaxf(0.f, xo - TAU * dot - TAU * c_sm[tid]);
                x_sm[tid] = xn;
                __stcg(&g_xbar[c0 + tid], 2.f * xn - xo);
            }
        }
        grid_barrier(++epoch);
    }

    // ---- Finalize: out = [x, lam, nu] ----
    if (tid < nc) out[c0 + tid] = x_sm[tid];
    if (tid < nr) {
        float l = fmaxf(0.f, -y_sm[tid]);
        __stcg(&g_lam[r0 + tid], l);
        out[N_DIM + r0 + tid] = l;
    }
    grid_barrier(++epoch);

    // nu = relu(c - A^T @ lam), against ORIGINAL fp32 A (one pass, accuracy)
    {
        float* s_lam = (float*)(sm + OFF_LAM);
        #pragma unroll
        for (int t = 0; t < 2; t++) {
            int i = t * NTHR + tid;
            if (i < M_DIM) s_lam[i] = __ldcg(&g_lam[i]);
        }
        __syncthreads();

        int g  = tid >> 6;
        int jc = tid & 63;
        if (jc < nc) {
            float acc = 0.f;
            for (int i = g; i < M_DIM; i += 16)
                acc += A[(size_t)i * N_DIM + c0 + jc] * s_lam[i];
            s_red[g * 64 + jc] = acc;
        }
        __syncthreads();
        if (tid < nc) {
            float dot = 0.f;
            #pragma unroll
            for (int gg = 0; gg < 16; gg++) dot += s_red[gg * 64 + tid];
            out[N_DIM + M_DIM + c0 + tid] = fmaxf(0.f, c_sm[tid] - dot);
        }
    }
}

// ---------------------------------------------------------------------------
// kernel_launch: 2 graph nodes (init, pdhg). Inputs (metadata order):
//   d_in[0] = c (8192), d_in[1] = A (2048*8192), d_in[2] = b (2048)
// Output: 18432 floats = concat(x[8192], lam[2048], nu[8192])
// ---------------------------------------------------------------------------
extern "C" void kernel_launch(void* const* d_in, const int* in_sizes, int n_in,
                              void* d_out, int out_size) {
    const float* c = (const float*)d_in[0];
    const float* A = (const float*)d_in[1];
    const float* b = (const float*)d_in[2];
    float* out = (float*)d_out;

    cudaFuncSetAttribute(pdhg_kernel,
                         cudaFuncAttributeMaxDynamicSharedMemorySize, SMEM_BYTES);

    init_kernel<<<32, 256>>>();
    pdhg_kernel<<<NBLK, NTHR, SMEM_BYTES>>>(A, b, c, out);
}